// round 1
// baseline (speedup 1.0000x reference)
#include <cuda_runtime.h>

#define HH 192
#define WW 192
#define HWSZ (192*192)
#define CC 64
#define KTAPS 49
#define PADK 3

// ---------------- scratch (no allocs allowed) ----------------
__device__ float g_rev [CC*HWSZ];
__device__ float g_e2  [CC*HWSZ];
__device__ float g_epre[CC*HWSZ];
__device__ float g_e3  [CC*HWSZ];
__device__ float g_weff[KTAPS*64*64];   // [k][c][o]
__device__ float g_wc2t[9*64*64];       // [k][c][o]
__device__ float g_wpot[4*64*64];       // [half*2+s][c][o]
__device__ float g_wpit[64*64];         // [j][c]
__device__ float g_gg  [64*64];         // [c][a*8+d]

// ---------------- precompute: FFT filter -> circular conv kernel ----------------
__global__ void k_prep_g(const float* __restrict__ fw) {
    int c = blockIdx.x;           // 64
    int t = threadIdx.x;          // 64 : a*8+d
    int a = t >> 3, d = t & 7;
    const float ct[8] = {1.f, 0.70710678118654752f, 0.f, -0.70710678118654752f,
                        -1.f, -0.70710678118654752f, 0.f, 0.70710678118654752f};
    const float st[8] = {0.f, 0.70710678118654752f, 1.f, 0.70710678118654752f,
                         0.f, -0.70710678118654752f, -1.f, -0.70710678118654752f};
    const float* w = fw + c * 40; // [8][5]
    float re = 0.f;
    for (int u = 0; u < 8; u++) {
        float rp = w[u*5+0] + ((d & 1) ? -w[u*5+4] : w[u*5+4]);
        float ip = 0.f;
        #pragma unroll
        for (int v = 1; v <= 3; v++) {
            int vd = (v * d) & 7;
            rp += 2.f * w[u*5+v] * ct[vd];
            ip += 2.f * w[u*5+v] * st[vd];
        }
        int ua = (u * a) & 7;
        re += ct[ua] * rp - st[ua] * ip;
    }
    g_gg[c*64 + t] = re * (1.f/64.f);
}

// ---------------- precompute: fused deform weight ----------------
__global__ void k_prep_weff(const float* __restrict__ wc1, const float* __restrict__ wd) {
    int idx = blockIdx.x * blockDim.x + threadIdx.x;   // k*4096 + c*64 + o
    if (idx >= KTAPS*64*64) return;
    int o = idx & 63, c = (idx >> 6) & 63, k = idx >> 12;
    float s = 0.f;
    for (int m = 0; m < 64; m++)
        s += wc1[o*64 + m] * wd[(m*64 + c)*49 + k];
    g_weff[idx] = s;
}

// ---------------- precompute: weight transposes ----------------
__global__ void k_prep_tr(const float* __restrict__ wc2, const float* __restrict__ wpo,
                          const float* __restrict__ wpi) {
    int idx = blockIdx.x * blockDim.x + threadIdx.x;
    if (idx < 9*4096) {                       // [k][c][o] <- wc2[o][c][k]
        int o = idx & 63, c = (idx >> 6) & 63, k = idx >> 12;
        g_wc2t[idx] = wc2[(o*64 + c)*9 + k];
    }
    if (idx < 4*4096) {                       // [half*2+s][c][o] <- wpo[half*64+o][s*64+c]
        int o = idx & 63, c = (idx >> 6) & 63, s = (idx >> 12) & 1, half = (idx >> 13) & 1;
        g_wpot[idx] = wpo[(half*64 + o)*128 + s*64 + c];
    }
    if (idx < 4096) {                         // [j][c] <- wpi[c][j]
        g_wpit[idx] = wpi[(idx & 63)*64 + (idx >> 6)];
    }
}

// ---------------- deform conv (+ fused 1x1) : implicit GEMM over 49 taps ----------------
__global__ void __launch_bounds__(256) k_deform(const float* __restrict__ enc,
                                                const float* __restrict__ off,
                                                const float* __restrict__ msk) {
    __shared__ float Wsh[64][64];     // [c][o]
    __shared__ float Vsh[64][64];     // [c][p]
    __shared__ int   sI[4][64];
    __shared__ float sW[4][64];

    int tid = threadIdx.x;
    int ph = blockIdx.y * 8, pw = blockIdx.x * 8;
    int ot = (tid >> 4) * 4;
    int pt = (tid & 15) * 4;

    float acc[4][4];
    #pragma unroll
    for (int i = 0; i < 4; i++)
        #pragma unroll
        for (int j = 0; j < 4; j++) acc[i][j] = 0.f;

    for (int k = 0; k < KTAPS; k++) {
        // stage weights
        const float4* wsrc = (const float4*)(g_weff + k*4096);
        float4* wdst = (float4*)&Wsh[0][0];
        #pragma unroll
        for (int i = 0; i < 4; i++) wdst[tid + i*256] = wsrc[tid + i*256];
        // stage sampling params (one thread per pixel)
        if (tid < 64) {
            int ly = tid >> 3, lx = tid & 7;
            int h = ph + ly, w = pw + lx;
            int sp = h * WW + w;
            float dy = off[(2*k)*HWSZ + sp];
            float dx = off[(2*k+1)*HWSZ + sp];
            float m  = msk[k*HWSZ + sp];
            float yy = (float)(h - PADK + k/7) + dy;
            float xx = (float)(w - PADK + k%7) + dx;
            float y0f = floorf(yy), x0f = floorf(xx);
            float wy = yy - y0f, wx = xx - x0f;
            int y0 = (int)y0f, x0 = (int)x0f;
            int y1 = y0 + 1,   x1 = x0 + 1;
            bool vy0 = (y0 >= 0) && (y0 < HH), vy1 = (y1 >= 0) && (y1 < HH);
            bool vx0 = (x0 >= 0) && (x0 < WW), vx1 = (x1 >= 0) && (x1 < WW);
            int y0c = min(max(y0, 0), HH-1), y1c = min(max(y1, 0), HH-1);
            int x0c = min(max(x0, 0), WW-1), x1c = min(max(x1, 0), WW-1);
            sI[0][tid] = y0c*WW + x0c;
            sI[1][tid] = y0c*WW + x1c;
            sI[2][tid] = y1c*WW + x0c;
            sI[3][tid] = y1c*WW + x1c;
            sW[0][tid] = (vy0 && vx0) ? (1.f-wy)*(1.f-wx)*m : 0.f;
            sW[1][tid] = (vy0 && vx1) ? (1.f-wy)*wx*m       : 0.f;
            sW[2][tid] = (vy1 && vx0) ? wy*(1.f-wx)*m       : 0.f;
            sW[3][tid] = (vy1 && vx1) ? wy*wx*m             : 0.f;
        }
        __syncthreads();
        // fill V: bilinear-gathered, mask-modulated samples
        #pragma unroll
        for (int i = 0; i < 16; i++) {
            int e = tid + i*256;
            int p = e & 63, c = e >> 6;
            const float* ep = enc + c*HWSZ;
            Vsh[c][p] = sW[0][p]*ep[sI[0][p]] + sW[1][p]*ep[sI[1][p]]
                      + sW[2][p]*ep[sI[2][p]] + sW[3][p]*ep[sI[3][p]];
        }
        __syncthreads();
        // accumulate O[64,64] += W[c][o]^T? (acc[o,p] += W[c][o]*V[c][p])
        #pragma unroll 16
        for (int c = 0; c < 64; c++) {
            float4 wv = *(const float4*)&Wsh[c][ot];
            float4 vv = *(const float4*)&Vsh[c][pt];
            acc[0][0] += wv.x*vv.x; acc[0][1] += wv.x*vv.y; acc[0][2] += wv.x*vv.z; acc[0][3] += wv.x*vv.w;
            acc[1][0] += wv.y*vv.x; acc[1][1] += wv.y*vv.y; acc[1][2] += wv.y*vv.z; acc[1][3] += wv.y*vv.w;
            acc[2][0] += wv.z*vv.x; acc[2][1] += wv.z*vv.y; acc[2][2] += wv.z*vv.z; acc[2][3] += wv.z*vv.w;
            acc[3][0] += wv.w*vv.x; acc[3][1] += wv.w*vv.y; acc[3][2] += wv.w*vv.z; acc[3][3] += wv.w*vv.w;
        }
        __syncthreads();
    }
    #pragma unroll
    for (int i = 0; i < 4; i++)
        #pragma unroll
        for (int j = 0; j < 4; j++) {
            int p = pt + j;
            int h = ph + (p >> 3), w = pw + (p & 7);
            g_rev[(ot+i)*HWSZ + h*WW + w] = acc[i][j];
        }
}

// ---------------- 1x1 conv on enc ----------------
__global__ void __launch_bounds__(256) k_conv1x1_in(const float* __restrict__ enc) {
    __shared__ float Wt[64][64];   // [j][c]
    int tid = threadIdx.x;
    #pragma unroll
    for (int i = 0; i < 16; i++) ((float*)Wt)[tid + i*256] = g_wpit[tid + i*256];
    __syncthreads();
    int p = blockIdx.x * 256 + tid;
    float acc[64];
    #pragma unroll
    for (int c = 0; c < 64; c++) acc[c] = 0.f;
    for (int j = 0; j < 64; j++) {
        float v = enc[j*HWSZ + p];
        #pragma unroll
        for (int c = 0; c < 64; c++) acc[c] += Wt[j][c] * v;
    }
    #pragma unroll
    for (int c = 0; c < 64; c++) g_e2[c*HWSZ + p] = acc[c];
}

// ---------------- per-patch circular conv (the FFT filter) + add rev ----------------
__global__ void __launch_bounds__(256) k_fftfilt() {
    __shared__ float E[64][64];           // [c][p]
    __shared__ float G[64][64];           // [c][a*8+d]
    __shared__ unsigned char T[64][64];   // [q][p] -> index into G row
    int tid = threadIdx.x;
    int ph = blockIdx.y * 8, pw = blockIdx.x * 8;

    #pragma unroll
    for (int i = 0; i < 16; i++) {
        int e = tid + i*256;
        int c = e >> 6, p = e & 63;
        E[c][p] = g_e2[c*HWSZ + (ph + (p >> 3))*WW + pw + (p & 7)];
        ((float*)G)[e] = g_gg[e];
        int q = e >> 6, pp = e & 63;
        T[q][pp] = (unsigned char)(((((pp >> 3) - (q >> 3)) & 7) << 3) | (((pp & 7) - (q & 7)) & 7));
    }
    __syncthreads();
    #pragma unroll
    for (int i = 0; i < 16; i++) {
        int e = tid + i*256;
        int c = e >> 6, p = e & 63;
        const float* gc = G[c];
        float s = 0.f;
        #pragma unroll 16
        for (int q = 0; q < 64; q++) s += E[c][q] * gc[T[q][p]];
        int h = ph + (p >> 3), w = pw + (p & 7);
        int gi = c*HWSZ + h*WW + w;
        g_epre[gi] = s + g_rev[gi];
    }
}

// ---------------- 3x3 conv (pad 1) as 9-tap implicit GEMM ----------------
__global__ void __launch_bounds__(256) k_conv3() {
    __shared__ float Wsh[64][64];
    __shared__ float Vsh[64][64];
    int tid = threadIdx.x;
    int ph = blockIdx.y * 8, pw = blockIdx.x * 8;
    int ot = (tid >> 4) * 4;
    int pt = (tid & 15) * 4;
    float acc[4][4];
    #pragma unroll
    for (int i = 0; i < 4; i++)
        #pragma unroll
        for (int j = 0; j < 4; j++) acc[i][j] = 0.f;

    for (int k = 0; k < 9; k++) {
        int dy = k/3 - 1, dx = k%3 - 1;
        const float4* wsrc = (const float4*)(g_wc2t + k*4096);
        float4* wdst = (float4*)&Wsh[0][0];
        #pragma unroll
        for (int i = 0; i < 4; i++) wdst[tid + i*256] = wsrc[tid + i*256];
        #pragma unroll
        for (int i = 0; i < 16; i++) {
            int e = tid + i*256;
            int p = e & 63, c = e >> 6;
            int h = ph + (p >> 3) + dy, w = pw + (p & 7) + dx;
            Vsh[c][p] = (h >= 0 && h < HH && w >= 0 && w < WW) ? g_epre[c*HWSZ + h*WW + w] : 0.f;
        }
        __syncthreads();
        #pragma unroll 16
        for (int c = 0; c < 64; c++) {
            float4 wv = *(const float4*)&Wsh[c][ot];
            float4 vv = *(const float4*)&Vsh[c][pt];
            acc[0][0] += wv.x*vv.x; acc[0][1] += wv.x*vv.y; acc[0][2] += wv.x*vv.z; acc[0][3] += wv.x*vv.w;
            acc[1][0] += wv.y*vv.x; acc[1][1] += wv.y*vv.y; acc[1][2] += wv.y*vv.z; acc[1][3] += wv.y*vv.w;
            acc[2][0] += wv.z*vv.x; acc[2][1] += wv.z*vv.y; acc[2][2] += wv.z*vv.z; acc[2][3] += wv.z*vv.w;
            acc[3][0] += wv.w*vv.x; acc[3][1] += wv.w*vv.y; acc[3][2] += wv.w*vv.z; acc[3][3] += wv.w*vv.w;
        }
        __syncthreads();
    }
    #pragma unroll
    for (int i = 0; i < 4; i++)
        #pragma unroll
        for (int j = 0; j < 4; j++) {
            int p = pt + j;
            int h = ph + (p >> 3), w = pw + (p & 7);
            g_e3[(ot+i)*HWSZ + h*WW + w] = acc[i][j];
        }
}

// ---------------- concat + 1x1 proj (128->128) + SimpleGate ----------------
__global__ void __launch_bounds__(256) k_projgate(const float* __restrict__ dec,
                                                  float* __restrict__ out) {
    __shared__ float W1[64][64];   // [c][o] rows 0..63  (x1)
    __shared__ float W2[64][64];   // [c][o] rows 64..127 (x2)
    __shared__ float Vsh[64][64];
    int tid = threadIdx.x;
    int ph = blockIdx.y * 8, pw = blockIdx.x * 8;
    int ot = (tid >> 4) * 4;
    int pt = (tid & 15) * 4;
    float a1[4][4], a2[4][4];
    #pragma unroll
    for (int i = 0; i < 4; i++)
        #pragma unroll
        for (int j = 0; j < 4; j++) { a1[i][j] = 0.f; a2[i][j] = 0.f; }

    for (int s = 0; s < 2; s++) {
        const float4* w1src = (const float4*)(g_wpot + (0*2 + s)*4096);
        const float4* w2src = (const float4*)(g_wpot + (1*2 + s)*4096);
        #pragma unroll
        for (int i = 0; i < 4; i++) {
            ((float4*)&W1[0][0])[tid + i*256] = w1src[tid + i*256];
            ((float4*)&W2[0][0])[tid + i*256] = w2src[tid + i*256];
        }
        #pragma unroll
        for (int i = 0; i < 16; i++) {
            int e = tid + i*256;
            int p = e & 63, c = e >> 6;
            int gi = c*HWSZ + (ph + (p >> 3))*WW + pw + (p & 7);
            Vsh[c][p] = (s == 0) ? g_e3[gi] : dec[gi];
        }
        __syncthreads();
        #pragma unroll 8
        for (int c = 0; c < 64; c++) {
            float4 w1 = *(const float4*)&W1[c][ot];
            float4 w2 = *(const float4*)&W2[c][ot];
            float4 vv = *(const float4*)&Vsh[c][pt];
            a1[0][0] += w1.x*vv.x; a1[0][1] += w1.x*vv.y; a1[0][2] += w1.x*vv.z; a1[0][3] += w1.x*vv.w;
            a1[1][0] += w1.y*vv.x; a1[1][1] += w1.y*vv.y; a1[1][2] += w1.y*vv.z; a1[1][3] += w1.y*vv.w;
            a1[2][0] += w1.z*vv.x; a1[2][1] += w1.z*vv.y; a1[2][2] += w1.z*vv.z; a1[2][3] += w1.z*vv.w;
            a1[3][0] += w1.w*vv.x; a1[3][1] += w1.w*vv.y; a1[3][2] += w1.w*vv.z; a1[3][3] += w1.w*vv.w;
            a2[0][0] += w2.x*vv.x; a2[0][1] += w2.x*vv.y; a2[0][2] += w2.x*vv.z; a2[0][3] += w2.x*vv.w;
            a2[1][0] += w2.y*vv.x; a2[1][1] += w2.y*vv.y; a2[1][2] += w2.y*vv.z; a2[1][3] += w2.y*vv.w;
            a2[2][0] += w2.z*vv.x; a2[2][1] += w2.z*vv.y; a2[2][2] += w2.z*vv.z; a2[2][3] += w2.z*vv.w;
            a2[3][0] += w2.w*vv.x; a2[3][1] += w2.w*vv.y; a2[3][2] += w2.w*vv.z; a2[3][3] += w2.w*vv.w;
        }
        __syncthreads();
    }
    #pragma unroll
    for (int i = 0; i < 4; i++)
        #pragma unroll
        for (int j = 0; j < 4; j++) {
            int p = pt + j;
            int h = ph + (p >> 3), w = pw + (p & 7);
            out[(ot+i)*HWSZ + h*WW + w] = a1[i][j] * a2[i][j];
        }
}

extern "C" void kernel_launch(void* const* d_in, const int* in_sizes, int n_in,
                              void* d_out, int out_size) {
    const float* enc  = (const float*)d_in[0];
    const float* dec  = (const float*)d_in[1];
    const float* ioff = (const float*)d_in[2];
    const float* iw   = (const float*)d_in[3];
    const float* wpi  = (const float*)d_in[4];
    const float* fftw = (const float*)d_in[5];
    const float* wpo  = (const float*)d_in[6];
    const float* wdef = (const float*)d_in[7];
    const float* wc1  = (const float*)d_in[8];
    const float* wc2  = (const float*)d_in[9];
    float* out = (float*)d_out;

    k_prep_g   <<<64, 64>>>(fftw);
    k_prep_weff<<<(KTAPS*4096 + 255)/256, 256>>>(wc1, wdef);
    k_prep_tr  <<<144, 256>>>(wc2, wpo, wpi);

    dim3 g24(24, 24);
    k_deform    <<<g24, 256>>>(enc, ioff, iw);
    k_conv1x1_in<<<144, 256>>>(enc);
    k_fftfilt   <<<g24, 256>>>();
    k_conv3     <<<g24, 256>>>();
    k_projgate  <<<g24, 256>>>(dec, out);
}

// round 2
// speedup vs baseline: 1.8331x; 1.8331x over previous
#include <cuda_runtime.h>

#define HH 192
#define WW 192
#define HWSZ (192*192)
#define CC 64
#define KTAPS 49
#define PADK 3

#define FMA2(d,a,b,c) asm("fma.rn.f32x2 %0, %1, %2, %3;" : "=l"(d) : "l"(a), "l"(b), "l"(c))

// ---------------- scratch (no allocs allowed) ----------------
__device__ float g_rev [CC*HWSZ];
__device__ float g_e2  [CC*HWSZ];
__device__ float g_epre[CC*HWSZ];
__device__ float g_e3  [CC*HWSZ];
__device__ float g_encT[HWSZ*CC];                    // NHWC
__device__ unsigned long long g_weff2[KTAPS*64*64];  // [k][c][o] replicated (w,w)
__device__ float g_wc2t[9*64*64];       // [k][c][o]
__device__ float g_wpot[4*64*64];       // [half*2+s][c][o]
__device__ float g_wpit[64*64];         // [j][c]
__device__ float g_gg  [64*64];         // [c][a*8+d]

// ---------------- precompute: FFT filter -> circular conv kernel ----------------
__global__ void k_prep_g(const float* __restrict__ fw) {
    int c = blockIdx.x;           // 64
    int t = threadIdx.x;          // 64 : a*8+d
    int a = t >> 3, d = t & 7;
    const float ct[8] = {1.f, 0.70710678118654752f, 0.f, -0.70710678118654752f,
                        -1.f, -0.70710678118654752f, 0.f, 0.70710678118654752f};
    const float st[8] = {0.f, 0.70710678118654752f, 1.f, 0.70710678118654752f,
                         0.f, -0.70710678118654752f, -1.f, -0.70710678118654752f};
    const float* w = fw + c * 40; // [8][5]
    float re = 0.f;
    for (int u = 0; u < 8; u++) {
        float rp = w[u*5+0] + ((d & 1) ? -w[u*5+4] : w[u*5+4]);
        float ip = 0.f;
        #pragma unroll
        for (int v = 1; v <= 3; v++) {
            int vd = (v * d) & 7;
            rp += 2.f * w[u*5+v] * ct[vd];
            ip += 2.f * w[u*5+v] * st[vd];
        }
        int ua = (u * a) & 7;
        re += ct[ua] * rp - st[ua] * ip;
    }
    g_gg[c*64 + t] = re * (1.f/64.f);
}

// ---------------- precompute: fused deform weight, replicated pairs ----------------
__global__ void k_prep_weff(const float* __restrict__ wc1, const float* __restrict__ wd) {
    int idx = blockIdx.x * blockDim.x + threadIdx.x;   // k*4096 + c*64 + o
    if (idx >= KTAPS*64*64) return;
    int o = idx & 63, c = (idx >> 6) & 63, k = idx >> 12;
    float s = 0.f;
    for (int m = 0; m < 64; m++)
        s += wc1[o*64 + m] * wd[(m*64 + c)*49 + k];
    unsigned int u = __float_as_uint(s);
    g_weff2[idx] = ((unsigned long long)u << 32) | u;
}

// ---------------- precompute: weight transposes ----------------
__global__ void k_prep_tr(const float* __restrict__ wc2, const float* __restrict__ wpo,
                          const float* __restrict__ wpi) {
    int idx = blockIdx.x * blockDim.x + threadIdx.x;
    if (idx < 9*4096) {                       // [k][c][o] <- wc2[o][c][k]
        int o = idx & 63, c = (idx >> 6) & 63, k = idx >> 12;
        g_wc2t[idx] = wc2[(o*64 + c)*9 + k];
    }
    if (idx < 4*4096) {                       // [half*2+s][c][o] <- wpo[half*64+o][s*64+c]
        int o = idx & 63, c = (idx >> 6) & 63, s = (idx >> 12) & 1, half = (idx >> 13) & 1;
        g_wpot[idx] = wpo[(half*64 + o)*128 + s*64 + c];
    }
    if (idx < 4096) {                         // [j][c] <- wpi[c][j]
        g_wpit[idx] = wpi[(idx & 63)*64 + (idx >> 6)];
    }
}

// ---------------- NCHW -> NHWC transpose of enc ----------------
__global__ void __launch_bounds__(256) k_transpose(const float* __restrict__ enc) {
    __shared__ float S[64][65];
    int tid = threadIdx.x;
    int p0 = blockIdx.x * 64;
    #pragma unroll
    for (int i = 0; i < 16; i++) {
        int e = i*256 + tid;
        int c = e >> 6, lp = e & 63;
        S[c][lp] = enc[c*HWSZ + p0 + lp];
    }
    __syncthreads();
    #pragma unroll
    for (int i = 0; i < 16; i++) {
        int e = i*256 + tid;           // e = lp*64 + c
        g_encT[p0*64 + e] = S[e & 63][e >> 6];
    }
}

// ---------------- deform conv (+ fused 1x1) : implicit GEMM, 16x16 tile ----------------
// smem layout (dynamic):
//   Vsh  : float[64][260]            66560 B
//   Wsh2 : ull  [64][64] replicated  32768 B
//   sIdx : int  [4][256]              4096 B
//   sWt  : float[4][256]              4096 B
#define DEF_SMEM (66560 + 32768 + 4096 + 4096)

__global__ void __launch_bounds__(256, 1) k_deform(const float* __restrict__ off,
                                                   const float* __restrict__ msk) {
    extern __shared__ char dsm[];
    float* Vsh = (float*)dsm;
    unsigned long long* Wsh2 = (unsigned long long*)(dsm + 66560);
    int*   sIdx = (int*)(dsm + 66560 + 32768);
    float* sWt  = (float*)(dsm + 66560 + 32768 + 4096);
    const float* encT = g_encT;

    int tid = threadIdx.x;
    int lane = tid & 31;
    int ot = (tid >> 5) * 8;           // warp-uniform o block
    int ph = blockIdx.y * 16, pw = blockIdx.x * 16;
    int ly = tid >> 4, lx = tid & 15;  // this thread's pixel for param stage
    int h = ph + ly, w = pw + lx;
    int sp = h * WW + w;

    unsigned long long acc[8][4];
    #pragma unroll
    for (int o = 0; o < 8; o++)
        #pragma unroll
        for (int pr = 0; pr < 4; pr++) acc[o][pr] = 0ull;

    for (int k = 0; k < KTAPS; k++) {
        // ---- stage weights (replicated pairs) ----
        {
            const ulonglong2* wsrc = (const ulonglong2*)(g_weff2 + k*4096);
            ulonglong2* wdst = (ulonglong2*)Wsh2;
            #pragma unroll
            for (int i = 0; i < 8; i++) wdst[tid + i*256] = wsrc[tid + i*256];
        }
        // ---- sampling params: one thread per pixel ----
        {
            float dy = off[(2*k)*HWSZ + sp];
            float dx = off[(2*k+1)*HWSZ + sp];
            float m  = msk[k*HWSZ + sp];
            float yy = (float)(h - PADK + k/7) + dy;
            float xx = (float)(w - PADK + k%7) + dx;
            float y0f = floorf(yy), x0f = floorf(xx);
            float wy = yy - y0f, wx = xx - x0f;
            int y0 = (int)y0f, x0 = (int)x0f;
            int y1 = y0 + 1,   x1 = x0 + 1;
            bool vy0 = (y0 >= 0) && (y0 < HH), vy1 = (y1 >= 0) && (y1 < HH);
            bool vx0 = (x0 >= 0) && (x0 < WW), vx1 = (x1 >= 0) && (x1 < WW);
            int y0c = min(max(y0, 0), HH-1), y1c = min(max(y1, 0), HH-1);
            int x0c = min(max(x0, 0), WW-1), x1c = min(max(x1, 0), WW-1);
            sIdx[0*256 + tid] = (y0c*WW + x0c) * 64;
            sIdx[1*256 + tid] = (y0c*WW + x1c) * 64;
            sIdx[2*256 + tid] = (y1c*WW + x0c) * 64;
            sIdx[3*256 + tid] = (y1c*WW + x1c) * 64;
            sWt[0*256 + tid] = (vy0 && vx0) ? (1.f-wy)*(1.f-wx)*m : 0.f;
            sWt[1*256 + tid] = (vy0 && vx1) ? (1.f-wy)*wx*m       : 0.f;
            sWt[2*256 + tid] = (vy1 && vx0) ? wy*(1.f-wx)*m       : 0.f;
            sWt[3*256 + tid] = (vy1 && vx1) ? wy*wx*m             : 0.f;
        }
        __syncthreads();

        // ---- gather: float4-over-channels, register transpose, STS.128 ----
        int c4 = tid & 15;
        #pragma unroll
        for (int it = 0; it < 4; it++) {
            int pq = (tid >> 4) + it * 16;   // 0..63
            int p0 = pq * 4;
            float4 r[4];
            #pragma unroll
            for (int pp = 0; pp < 4; pp++) {
                int p = p0 + pp;
                const float4 t0 = *(const float4*)(encT + sIdx[0*256 + p] + (c4 << 2));
                const float4 t1 = *(const float4*)(encT + sIdx[1*256 + p] + (c4 << 2));
                const float4 t2 = *(const float4*)(encT + sIdx[2*256 + p] + (c4 << 2));
                const float4 t3 = *(const float4*)(encT + sIdx[3*256 + p] + (c4 << 2));
                float w0 = sWt[0*256 + p], w1 = sWt[1*256 + p];
                float w2 = sWt[2*256 + p], w3 = sWt[3*256 + p];
                r[pp].x = w0*t0.x + w1*t1.x + w2*t2.x + w3*t3.x;
                r[pp].y = w0*t0.y + w1*t1.y + w2*t2.y + w3*t3.y;
                r[pp].z = w0*t0.z + w1*t1.z + w2*t2.z + w3*t3.z;
                r[pp].w = w0*t0.w + w1*t1.w + w2*t2.w + w3*t3.w;
            }
            // transpose 4x4 -> rows are channels
            float4 o0 = make_float4(r[0].x, r[1].x, r[2].x, r[3].x);
            float4 o1 = make_float4(r[0].y, r[1].y, r[2].y, r[3].y);
            float4 o2 = make_float4(r[0].z, r[1].z, r[2].z, r[3].z);
            float4 o3 = make_float4(r[0].w, r[1].w, r[2].w, r[3].w);
            *(float4*)&Vsh[(c4*4 + 0)*260 + p0] = o0;
            *(float4*)&Vsh[(c4*4 + 1)*260 + p0] = o1;
            *(float4*)&Vsh[(c4*4 + 2)*260 + p0] = o2;
            *(float4*)&Vsh[(c4*4 + 3)*260 + p0] = o3;
        }
        __syncthreads();

        // ---- GEMM: acc[o][p] += W[c][o] * V[c][p], f32x2 packed ----
        #pragma unroll 8
        for (int c = 0; c < 64; c++) {
            union { float4 f; unsigned long long u[2]; } A, B;
            A.f = *(const float4*)&Vsh[c*260 + 4*lane];
            B.f = *(const float4*)&Vsh[c*260 + 128 + 4*lane];
            const ulonglong2* wp = (const ulonglong2*)(Wsh2 + c*64 + ot);
            ulonglong2 w01 = wp[0], w23 = wp[1], w45 = wp[2], w67 = wp[3];
            unsigned long long wv[8] = {w01.x, w01.y, w23.x, w23.y,
                                        w45.x, w45.y, w67.x, w67.y};
            #pragma unroll
            for (int o = 0; o < 8; o++) {
                FMA2(acc[o][0], wv[o], A.u[0], acc[o][0]);
                FMA2(acc[o][1], wv[o], A.u[1], acc[o][1]);
                FMA2(acc[o][2], wv[o], B.u[0], acc[o][2]);
                FMA2(acc[o][3], wv[o], B.u[1], acc[o][3]);
            }
        }
        __syncthreads();
    }

    // ---- write out: thread owns p in {4*lane..+3, 128+4*lane..+3} ----
    #pragma unroll
    for (int o = 0; o < 8; o++) {
        float* orow = g_rev + (ot + o)*HWSZ;
        #pragma unroll
        for (int pr = 0; pr < 4; pr++) {
            unsigned int ulo = (unsigned int)(acc[o][pr] & 0xffffffffull);
            unsigned int uhi = (unsigned int)(acc[o][pr] >> 32);
            int pbase = ((pr >> 1) ? 128 : 0) + 4*lane + (pr & 1)*2;
            int p0 = pbase, p1 = pbase + 1;
            orow[(ph + (p0 >> 4))*WW + pw + (p0 & 15)] = __uint_as_float(ulo);
            orow[(ph + (p1 >> 4))*WW + pw + (p1 & 15)] = __uint_as_float(uhi);
        }
    }
}

// ---------------- 1x1 conv on enc ----------------
__global__ void __launch_bounds__(256) k_conv1x1_in(const float* __restrict__ enc) {
    __shared__ float Wt[64][64];   // [j][c]
    int tid = threadIdx.x;
    #pragma unroll
    for (int i = 0; i < 16; i++) ((float*)Wt)[tid + i*256] = g_wpit[tid + i*256];
    __syncthreads();
    int p = blockIdx.x * 256 + tid;
    float acc[64];
    #pragma unroll
    for (int c = 0; c < 64; c++) acc[c] = 0.f;
    for (int j = 0; j < 64; j++) {
        float v = enc[j*HWSZ + p];
        #pragma unroll
        for (int c = 0; c < 64; c++) acc[c] += Wt[j][c] * v;
    }
    #pragma unroll
    for (int c = 0; c < 64; c++) g_e2[c*HWSZ + p] = acc[c];
}

// ---------------- per-patch circular conv (the FFT filter) + add rev ----------------
__global__ void __launch_bounds__(256) k_fftfilt() {
    __shared__ float E[64][64];           // [c][p]
    __shared__ float G[64][64];           // [c][a*8+d]
    __shared__ unsigned char T[64][64];   // [q][p] -> index into G row
    int tid = threadIdx.x;
    int ph = blockIdx.y * 8, pw = blockIdx.x * 8;

    #pragma unroll
    for (int i = 0; i < 16; i++) {
        int e = tid + i*256;
        int c = e >> 6, p = e & 63;
        E[c][p] = g_e2[c*HWSZ + (ph + (p >> 3))*WW + pw + (p & 7)];
        ((float*)G)[e] = g_gg[e];
        int q = e >> 6, pp = e & 63;
        T[q][pp] = (unsigned char)(((((pp >> 3) - (q >> 3)) & 7) << 3) | (((pp & 7) - (q & 7)) & 7));
    }
    __syncthreads();
    #pragma unroll
    for (int i = 0; i < 16; i++) {
        int e = tid + i*256;
        int c = e >> 6, p = e & 63;
        const float* gc = G[c];
        float s = 0.f;
        #pragma unroll 16
        for (int q = 0; q < 64; q++) s += E[c][q] * gc[T[q][p]];
        int h = ph + (p >> 3), w = pw + (p & 7);
        int gi = c*HWSZ + h*WW + w;
        g_epre[gi] = s + g_rev[gi];
    }
}

// ---------------- 3x3 conv (pad 1) as 9-tap implicit GEMM ----------------
__global__ void __launch_bounds__(256) k_conv3() {
    __shared__ float Wsh[64][64];
    __shared__ float Vsh[64][64];
    int tid = threadIdx.x;
    int ph = blockIdx.y * 8, pw = blockIdx.x * 8;
    int ot = (tid >> 4) * 4;
    int pt = (tid & 15) * 4;
    float acc[4][4];
    #pragma unroll
    for (int i = 0; i < 4; i++)
        #pragma unroll
        for (int j = 0; j < 4; j++) acc[i][j] = 0.f;

    for (int k = 0; k < 9; k++) {
        int dy = k/3 - 1, dx = k%3 - 1;
        const float4* wsrc = (const float4*)(g_wc2t + k*4096);
        float4* wdst = (float4*)&Wsh[0][0];
        #pragma unroll
        for (int i = 0; i < 4; i++) wdst[tid + i*256] = wsrc[tid + i*256];
        #pragma unroll
        for (int i = 0; i < 16; i++) {
            int e = tid + i*256;
            int p = e & 63, c = e >> 6;
            int h = ph + (p >> 3) + dy, w = pw + (p & 7) + dx;
            Vsh[c][p] = (h >= 0 && h < HH && w >= 0 && w < WW) ? g_epre[c*HWSZ + h*WW + w] : 0.f;
        }
        __syncthreads();
        #pragma unroll 16
        for (int c = 0; c < 64; c++) {
            float4 wv = *(const float4*)&Wsh[c][ot];
            float4 vv = *(const float4*)&Vsh[c][pt];
            acc[0][0] += wv.x*vv.x; acc[0][1] += wv.x*vv.y; acc[0][2] += wv.x*vv.z; acc[0][3] += wv.x*vv.w;
            acc[1][0] += wv.y*vv.x; acc[1][1] += wv.y*vv.y; acc[1][2] += wv.y*vv.z; acc[1][3] += wv.y*vv.w;
            acc[2][0] += wv.z*vv.x; acc[2][1] += wv.z*vv.y; acc[2][2] += wv.z*vv.z; acc[2][3] += wv.z*vv.w;
            acc[3][0] += wv.w*vv.x; acc[3][1] += wv.w*vv.y; acc[3][2] += wv.w*vv.z; acc[3][3] += wv.w*vv.w;
        }
        __syncthreads();
    }
    #pragma unroll
    for (int i = 0; i < 4; i++)
        #pragma unroll
        for (int j = 0; j < 4; j++) {
            int p = pt + j;
            int h = ph + (p >> 3), w = pw + (p & 7);
            g_e3[(ot+i)*HWSZ + h*WW + w] = acc[i][j];
        }
}

// ---------------- concat + 1x1 proj (128->128) + SimpleGate ----------------
__global__ void __launch_bounds__(256) k_projgate(const float* __restrict__ dec,
                                                  float* __restrict__ out) {
    __shared__ float W1[64][64];   // [c][o] rows 0..63  (x1)
    __shared__ float W2[64][64];   // [c][o] rows 64..127 (x2)
    __shared__ float Vsh[64][64];
    int tid = threadIdx.x;
    int ph = blockIdx.y * 8, pw = blockIdx.x * 8;
    int ot = (tid >> 4) * 4;
    int pt = (tid & 15) * 4;
    float a1[4][4], a2[4][4];
    #pragma unroll
    for (int i = 0; i < 4; i++)
        #pragma unroll
        for (int j = 0; j < 4; j++) { a1[i][j] = 0.f; a2[i][j] = 0.f; }

    for (int s = 0; s < 2; s++) {
        const float4* w1src = (const float4*)(g_wpot + (0*2 + s)*4096);
        const float4* w2src = (const float4*)(g_wpot + (1*2 + s)*4096);
        #pragma unroll
        for (int i = 0; i < 4; i++) {
            ((float4*)&W1[0][0])[tid + i*256] = w1src[tid + i*256];
            ((float4*)&W2[0][0])[tid + i*256] = w2src[tid + i*256];
        }
        #pragma unroll
        for (int i = 0; i < 16; i++) {
            int e = tid + i*256;
            int p = e & 63, c = e >> 6;
            int gi = c*HWSZ + (ph + (p >> 3))*WW + pw + (p & 7);
            Vsh[c][p] = (s == 0) ? g_e3[gi] : dec[gi];
        }
        __syncthreads();
        #pragma unroll 8
        for (int c = 0; c < 64; c++) {
            float4 w1 = *(const float4*)&W1[c][ot];
            float4 w2 = *(const float4*)&W2[c][ot];
            float4 vv = *(const float4*)&Vsh[c][pt];
            a1[0][0] += w1.x*vv.x; a1[0][1] += w1.x*vv.y; a1[0][2] += w1.x*vv.z; a1[0][3] += w1.x*vv.w;
            a1[1][0] += w1.y*vv.x; a1[1][1] += w1.y*vv.y; a1[1][2] += w1.y*vv.z; a1[1][3] += w1.y*vv.w;
            a1[2][0] += w1.z*vv.x; a1[2][1] += w1.z*vv.y; a1[2][2] += w1.z*vv.z; a1[2][3] += w1.z*vv.w;
            a1[3][0] += w1.w*vv.x; a1[3][1] += w1.w*vv.y; a1[3][2] += w1.w*vv.z; a1[3][3] += w1.w*vv.w;
            a2[0][0] += w2.x*vv.x; a2[0][1] += w2.x*vv.y; a2[0][2] += w2.x*vv.z; a2[0][3] += w2.x*vv.w;
            a2[1][0] += w2.y*vv.x; a2[1][1] += w2.y*vv.y; a2[1][2] += w2.y*vv.z; a2[1][3] += w2.y*vv.w;
            a2[2][0] += w2.z*vv.x; a2[2][1] += w2.z*vv.y; a2[2][2] += w2.z*vv.z; a2[2][3] += w2.z*vv.w;
            a2[3][0] += w2.w*vv.x; a2[3][1] += w2.w*vv.y; a2[3][2] += w2.w*vv.z; a2[3][3] += w2.w*vv.w;
        }
        __syncthreads();
    }
    #pragma unroll
    for (int i = 0; i < 4; i++)
        #pragma unroll
        for (int j = 0; j < 4; j++) {
            int p = pt + j;
            int h = ph + (p >> 3), w = pw + (p & 7);
            out[(ot+i)*HWSZ + h*WW + w] = a1[i][j] * a2[i][j];
        }
}

extern "C" void kernel_launch(void* const* d_in, const int* in_sizes, int n_in,
                              void* d_out, int out_size) {
    const float* enc  = (const float*)d_in[0];
    const float* dec  = (const float*)d_in[1];
    const float* ioff = (const float*)d_in[2];
    const float* iw   = (const float*)d_in[3];
    const float* wpi  = (const float*)d_in[4];
    const float* fftw = (const float*)d_in[5];
    const float* wpo  = (const float*)d_in[6];
    const float* wdef = (const float*)d_in[7];
    const float* wc1  = (const float*)d_in[8];
    const float* wc2  = (const float*)d_in[9];
    float* out = (float*)d_out;

    cudaFuncSetAttribute(k_deform, cudaFuncAttributeMaxDynamicSharedMemorySize, DEF_SMEM);

    k_prep_g   <<<64, 64>>>(fftw);
    k_prep_weff<<<(KTAPS*4096 + 255)/256, 256>>>(wc1, wdef);
    k_prep_tr  <<<144, 256>>>(wc2, wpo, wpi);
    k_transpose<<<576, 256>>>(enc);

    dim3 g12(12, 12);
    dim3 g24(24, 24);
    k_deform    <<<g12, 256, DEF_SMEM>>>(ioff, iw);
    k_conv1x1_in<<<144, 256>>>(enc);
    k_fftfilt   <<<g24, 256>>>();
    k_conv3     <<<g24, 256>>>();
    k_projgate  <<<g24, 256>>>(dec, out);
}